// round 1
// baseline (speedup 1.0000x reference)
#include <cuda_runtime.h>

#define BS 32
#define LA 300
#define LB 1024
#define H  512
#define NROW (H*H)   // 262144 rows of W2d

// ---------------- scratch (static device globals; no allocations) ----------------
__device__ float g_part[BS*8*H];          // partial sums for b_mean
__device__ float g_bm[BS*H];              // b_mean [b][e]
__device__ float g_T2[(long)NROW*BS];     // [(k*H+d)][b]   (33.5 MB)
__device__ float g_T[(long)BS*NROW];      // [b][k*H+d]     (33.5 MB)

// ---------------- f32x2 helpers (sm_103a packed fp32) ----------------
__device__ __forceinline__ unsigned long long pack2(float x, float y) {
    unsigned long long r;
    unsigned int a = __float_as_uint(x), b = __float_as_uint(y);
    asm("mov.b64 %0, {%1, %2};" : "=l"(r) : "r"(a), "r"(b));
    return r;
}
__device__ __forceinline__ unsigned long long packdup(float x) {
    unsigned long long r;
    unsigned int a = __float_as_uint(x);
    asm("mov.b64 %0, {%1, %1};" : "=l"(r) : "r"(a));
    return r;
}
__device__ __forceinline__ unsigned long long fma2(unsigned long long a,
                                                   unsigned long long b,
                                                   unsigned long long c) {
    unsigned long long d;
    asm("fma.rn.f32x2 %0, %1, %2, %3;" : "=l"(d) : "l"(a), "l"(b), "l"(c));
    return d;
}
__device__ __forceinline__ float2 unpack2(unsigned long long v) {
    unsigned int a, b;
    asm("mov.b64 {%0, %1}, %2;" : "=r"(a), "=r"(b) : "l"(v));
    return make_float2(__uint_as_float(a), __uint_as_float(b));
}

// ---------------- kernel 1: b_mean partials ----------------
// grid (8 chunks, 32 batches), 512 threads
__global__ void k_bmean_part(const float* __restrict__ feat_b) {
    int chunk = blockIdx.x, b = blockIdx.y, d = threadIdx.x;
    const float* p = feat_b + ((long)b*LB + (long)chunk*128)*H + d;
    float s = 0.f;
    #pragma unroll 8
    for (int j = 0; j < 128; j++) s += p[(long)j*H];
    g_part[((long)b*8 + chunk)*H + d] = s;
}

// grid 32, 512 threads
__global__ void k_bmean_red() {
    long idx = (long)blockIdx.x*512 + threadIdx.x;   // b*H + d
    long b = idx >> 9, d = idx & 511;
    float s = 0.f;
    #pragma unroll
    for (int c = 0; c < 8; c++) s += g_part[(b*8 + c)*H + d];
    g_bm[idx] = s * (1.0f/1024.0f);
}

// ---------------- kernel 2: T2[r][b] = sum_e W2d[r][e]*bm[b][e] ----------------
// grid 256 blocks * 1024 rows, 256 threads, 4 rows/thread, 32 batches as 16 f32x2 acc
__global__ void __launch_bounds__(256, 1) k_wgemm(const float4* __restrict__ W4) {
    extern __shared__ unsigned long long s_bm[];   // [e][n2] = 512*16 ULL = 64KB
    int tid = threadIdx.x;

    for (int i = tid; i < H*16; i += 256) {
        int e = i >> 4, n2 = i & 15;
        s_bm[i] = pack2(g_bm[(2*n2)*H + e], g_bm[(2*n2+1)*H + e]);
    }
    __syncthreads();

    long r0 = (long)blockIdx.x*1024 + tid;          // rows r0 + {0,256,512,768}
    const float4* Wr = W4 + r0*128;                 // 128 float4 per row (e=512)

    unsigned long long acc[4][16];
    #pragma unroll
    for (int i = 0; i < 4; i++)
        #pragma unroll
        for (int n2 = 0; n2 < 16; n2++) acc[i][n2] = 0ull;

    #pragma unroll 1
    for (int e4 = 0; e4 < 128; e4++) {
        float4 w0 = __ldg(Wr + e4);
        float4 w1 = __ldg(Wr + 256*128 + e4);
        float4 w2 = __ldg(Wr + 512*128 + e4);
        float4 w3 = __ldg(Wr + 768*128 + e4);
        float wl[16] = {w0.x,w0.y,w0.z,w0.w, w1.x,w1.y,w1.z,w1.w,
                        w2.x,w2.y,w2.z,w2.w, w3.x,w3.y,w3.z,w3.w};
        #pragma unroll
        for (int u = 0; u < 4; u++) {
            unsigned long long wp0 = packdup(wl[0*4+u]);
            unsigned long long wp1 = packdup(wl[1*4+u]);
            unsigned long long wp2 = packdup(wl[2*4+u]);
            unsigned long long wp3 = packdup(wl[3*4+u]);
            const unsigned long long* bp = &s_bm[(e4*4+u)*16];
            #pragma unroll
            for (int n2 = 0; n2 < 16; n2++) {
                unsigned long long bb = bp[n2];
                acc[0][n2] = fma2(wp0, bb, acc[0][n2]);
                acc[1][n2] = fma2(wp1, bb, acc[1][n2]);
                acc[2][n2] = fma2(wp2, bb, acc[2][n2]);
                acc[3][n2] = fma2(wp3, bb, acc[3][n2]);
            }
        }
    }

    #pragma unroll
    for (int i = 0; i < 4; i++) {
        float4* out = reinterpret_cast<float4*>(&g_T2[(r0 + i*256)*32]);
        #pragma unroll
        for (int q = 0; q < 8; q++) {
            float2 lo = unpack2(acc[i][2*q]);
            float2 hi = unpack2(acc[i][2*q+1]);
            out[q] = make_float4(lo.x, lo.y, hi.x, hi.y);
        }
    }
}

// ---------------- kernel T: transpose T2 [r][b] -> T [b][r] ----------------
// grid 2048 blocks * 128 rows, 256 threads
__global__ void k_transpose() {
    __shared__ float s[128][33];
    int tid = threadIdx.x;
    long rbase = (long)blockIdx.x*128;
    #pragma unroll
    for (int i = 0; i < 16; i++) {
        int idx = tid + i*256;
        int r = idx >> 5, n = idx & 31;
        s[r][n] = g_T2[(rbase + r)*32 + n];
    }
    __syncthreads();
    #pragma unroll
    for (int i = 0; i < 16; i++) {
        int idx = tid + i*256;
        int n = idx >> 7, rl = idx & 127;
        g_T[(long)n*NROW + rbase + rl] = s[rl][n];
    }
}

// ---------------- kernel 3: fused = feat_a @ T^T (+bias +feat_a), write x ----------------
#define BM 64
#define BN 128
#define BKK 32
// grid (4 ktiles, 5 rowtiles, 32 batches), 256 threads
__global__ void __launch_bounds__(256) k_gemm2(const float* __restrict__ A,
                                               const float* __restrict__ bias,
                                               float* __restrict__ out) {
    __shared__ float sA[BKK][68];       // [dd][row], pad to 68 (16B-aligned rows)
    __shared__ float sB[BKK][BN+4];     // [dd][col], pad to 132 (16B-aligned rows)
    int b = blockIdx.z, rt = blockIdx.y, kt = blockIdx.x;
    int tid = threadIdx.x;
    int tx = tid & 15;        // col group: cols tx*8 .. +7
    int ty = tid >> 4;        // row group: rows ty*4 .. +3
    int row0 = rt*BM;
    const float* Ab = A + (long)b*LA*H;
    const float* Bb = g_T + (long)b*NROW + (long)kt*BN*H;

    unsigned long long acc[4][4];
    #pragma unroll
    for (int i = 0; i < 4; i++)
        #pragma unroll
        for (int j = 0; j < 4; j++) acc[i][j] = 0ull;

    for (int kc = 0; kc < H; kc += BKK) {
        #pragma unroll
        for (int i = 0; i < 8; i++) {           // A tile: 64x32
            int idx = tid + i*256;
            int r = idx >> 5, dd = idx & 31;
            int ar = row0 + r;
            sA[dd][r] = (ar < LA) ? Ab[(long)ar*H + kc + dd] : 0.f;
        }
        #pragma unroll
        for (int i = 0; i < 16; i++) {          // B tile: 128x32
            int idx = tid + i*256;
            int c = idx >> 5, dd = idx & 31;
            sB[dd][c] = Bb[(long)c*H + kc + dd];
        }
        __syncthreads();
        #pragma unroll
        for (int kk = 0; kk < BKK; kk++) {
            float4 a4 = *reinterpret_cast<const float4*>(&sA[kk][ty*4]);
            ulonglong2 b01 = *reinterpret_cast<const ulonglong2*>(&sB[kk][tx*8]);
            ulonglong2 b23 = *reinterpret_cast<const ulonglong2*>(&sB[kk][tx*8+4]);
            unsigned long long bp0 = b01.x, bp1 = b01.y, bp2 = b23.x, bp3 = b23.y;
            float av[4] = {a4.x, a4.y, a4.z, a4.w};
            #pragma unroll
            for (int i = 0; i < 4; i++) {
                unsigned long long ap = packdup(av[i]);
                acc[i][0] = fma2(ap, bp0, acc[i][0]);
                acc[i][1] = fma2(ap, bp1, acc[i][1]);
                acc[i][2] = fma2(ap, bp2, acc[i][2]);
                acc[i][3] = fma2(ap, bp3, acc[i][3]);
            }
        }
        __syncthreads();
    }

    int k0 = kt*BN + tx*8;
    #pragma unroll
    for (int i = 0; i < 4; i++) {
        int ar = row0 + ty*4 + i;
        if (ar < LA) {
            const float* arow = Ab + (long)ar*H + k0;
            float* orow = out + ((long)b*LA + ar)*H + k0;
            float2 p0 = unpack2(acc[i][0]), p1 = unpack2(acc[i][1]);
            float2 p2 = unpack2(acc[i][2]), p3 = unpack2(acc[i][3]);
            float v[8] = {p0.x,p0.y,p1.x,p1.y,p2.x,p2.y,p3.x,p3.y};
            #pragma unroll
            for (int q = 0; q < 8; q++)
                orow[q] = v[q] + bias[k0+q] + arow[q];
        }
    }
}

// ---------------- kernel 4: row LayerNorm in-place on d_out ----------------
// grid 9600, 128 threads (4 floats each)
__global__ void k_ln(const float* __restrict__ gamma, const float* __restrict__ beta,
                     float* __restrict__ out) {
    __shared__ float ssum[4], ssq[4];
    long row = blockIdx.x;
    int tid = threadIdx.x;
    float4* xr = reinterpret_cast<float4*>(out + row*H);
    float4 v = xr[tid];
    float s  = v.x + v.y + v.z + v.w;
    float sq = v.x*v.x + v.y*v.y + v.z*v.z + v.w*v.w;
    #pragma unroll
    for (int o = 16; o > 0; o >>= 1) {
        s  += __shfl_xor_sync(0xffffffffu, s,  o);
        sq += __shfl_xor_sync(0xffffffffu, sq, o);
    }
    int wid = tid >> 5;
    if ((tid & 31) == 0) { ssum[wid] = s; ssq[wid] = sq; }
    __syncthreads();
    float stot = ssum[0] + ssum[1] + ssum[2] + ssum[3];
    float sqtot = ssq[0] + ssq[1] + ssq[2] + ssq[3];
    float mu = stot * (1.0f/H);
    float var = sqtot * (1.0f/H) - mu*mu;
    float rstd = rsqrtf(var + 1e-5f);
    const float4 g4 = reinterpret_cast<const float4*>(gamma)[tid];
    const float4 b4 = reinterpret_cast<const float4*>(beta)[tid];
    v.x = (v.x - mu)*rstd*g4.x + b4.x;
    v.y = (v.y - mu)*rstd*g4.y + b4.y;
    v.z = (v.z - mu)*rstd*g4.z + b4.z;
    v.w = (v.w - mu)*rstd*g4.w + b4.w;
    xr[tid] = v;
}

// ---------------- launch ----------------
extern "C" void kernel_launch(void* const* d_in, const int* in_sizes, int n_in,
                              void* d_out, int out_size) {
    const float* feat_a = (const float*)d_in[0];
    const float* feat_b = (const float*)d_in[1];
    const float* W      = (const float*)d_in[2];
    const float* bias   = (const float*)d_in[3];
    const float* gamma  = (const float*)d_in[4];
    const float* beta   = (const float*)d_in[5];
    float* out = (float*)d_out;

    static bool attr_done = false;
    if (!attr_done) {
        cudaFuncSetAttribute(k_wgemm, cudaFuncAttributeMaxDynamicSharedMemorySize, 65536);
        attr_done = true;
    }

    k_bmean_part<<<dim3(8,32), 512>>>(feat_b);
    k_bmean_red<<<32, 512>>>();
    k_wgemm<<<256, 256, 65536>>>((const float4*)W);
    k_transpose<<<2048, 256>>>();
    k_gemm2<<<dim3(4,5,32), 256>>>(feat_a, bias, out);
    k_ln<<<9600, 128>>>(gamma, beta, out);
}

// round 2
// speedup vs baseline: 1.2528x; 1.2528x over previous
#include <cuda_runtime.h>

#define BS 32
#define LA 300
#define LB 1024
#define H  512
#define NROW (H*H)   // 262144 rows of W2d

// ---------------- scratch ----------------
__device__ float g_part[BS*8*H];
__device__ float g_bm[BS*H];
__device__ float g_T[(long)BS*NROW];     // [b][k*H+d]  33.5 MB

// ---------------- f32x2 helpers ----------------
__device__ __forceinline__ unsigned long long pack2(float x, float y) {
    unsigned long long r;
    unsigned int a = __float_as_uint(x), b = __float_as_uint(y);
    asm("mov.b64 %0, {%1, %2};" : "=l"(r) : "r"(a), "r"(b));
    return r;
}
__device__ __forceinline__ unsigned long long packdup(float x) {
    unsigned long long r;
    unsigned int a = __float_as_uint(x);
    asm("mov.b64 %0, {%1, %1};" : "=l"(r) : "r"(a));
    return r;
}
__device__ __forceinline__ unsigned long long fma2(unsigned long long a,
                                                   unsigned long long b,
                                                   unsigned long long c) {
    unsigned long long d;
    asm("fma.rn.f32x2 %0, %1, %2, %3;" : "=l"(d) : "l"(a), "l"(b), "l"(c));
    return d;
}
__device__ __forceinline__ float2 unpack2(unsigned long long v) {
    unsigned int a, b;
    asm("mov.b64 {%0, %1}, %2;" : "=r"(a), "=r"(b) : "l"(v));
    return make_float2(__uint_as_float(a), __uint_as_float(b));
}

// ---------------- kernel 1: b_mean ----------------
__global__ void k_bmean_part(const float* __restrict__ feat_b) {
    int chunk = blockIdx.x, b = blockIdx.y, d = threadIdx.x;
    const float* p = feat_b + ((long)b*LB + (long)chunk*128)*H + d;
    float s = 0.f;
    #pragma unroll 8
    for (int j = 0; j < 128; j++) s += p[(long)j*H];
    g_part[((long)b*8 + chunk)*H + d] = s;
}
__global__ void k_bmean_red() {
    long idx = (long)blockIdx.x*512 + threadIdx.x;
    long b = idx >> 9;
    long d = idx & 511;
    float s = 0.f;
    #pragma unroll
    for (int c = 0; c < 8; c++) s += g_part[(b*8 + c)*H + d];
    g_bm[idx] = s * (1.0f/1024.0f);
}

// ---------------- kernel 2: T[b][r] = sum_e W2d[r][e]*bm[b][e] ----------------
// 256 CTAs x 256 thr. CTA: 1024 rows. Thread: rows tid+{0,256,512,768} x 32 batches.
// smem: s_bm ULL[512][16] (64KB) + sW f32 [2][1024][20] (160KB) = 229376 B.
#define WGC 32            // number of K chunks (512/16)
#define SWS 20            // smem row stride in words (16 data + 4 pad; 16B aligned; /4 odd)

__device__ __forceinline__ void wg_prefetch(const float* __restrict__ Wg, long r0,
                                            int kc, float* dst, int tid) {
    #pragma unroll
    for (int p = 0; p < 16; p++) {
        int idx = p*256 + tid;
        int row = idx >> 2, c = idx & 3;
        const float* g = Wg + (r0 + row)*H + kc*16 + c*4;
        unsigned saddr = (unsigned)__cvta_generic_to_shared(dst + row*SWS + c*4);
        asm volatile("cp.async.cg.shared.global [%0], [%1], 16;" :: "r"(saddr), "l"(g));
    }
    asm volatile("cp.async.commit_group;" ::: "memory");
}

__global__ void __launch_bounds__(256, 1) k_wgemm(const float* __restrict__ Wg) {
    extern __shared__ char smem_raw[];
    unsigned long long* s_bm = (unsigned long long*)smem_raw;    // [e][16]
    float* sW = (float*)(smem_raw + 65536);                      // [2][1024][SWS]
    int tid = threadIdx.x;
    long r0 = (long)blockIdx.x * 1024;

    for (int i = tid; i < 512*16; i += 256) {
        int e = i >> 4, n2 = i & 15;
        s_bm[i] = pack2(g_bm[(2*n2)*H + e], g_bm[(2*n2+1)*H + e]);
    }

    wg_prefetch(Wg, r0, 0, sW, tid);

    unsigned long long acc[4][16];
    #pragma unroll
    for (int i = 0; i < 4; i++)
        #pragma unroll
        for (int n2 = 0; n2 < 16; n2++) acc[i][n2] = 0ull;

    __syncthreads();   // bm ready

    for (int kc = 0; kc < WGC; kc++) {
        if (kc + 1 < WGC)
            wg_prefetch(Wg, r0, kc+1, sW + ((kc+1)&1)*1024*SWS, tid);
        if (kc + 1 < WGC) asm volatile("cp.async.wait_group 1;" ::: "memory");
        else              asm volatile("cp.async.wait_group 0;" ::: "memory");
        __syncthreads();

        const float* wb = sW + (kc&1)*1024*SWS + tid*SWS;
        #pragma unroll
        for (int q = 0; q < 4; q++) {
            float4 w0 = *(const float4*)(wb + 0*256*SWS + q*4);
            float4 w1 = *(const float4*)(wb + 1*256*SWS + q*4);
            float4 w2 = *(const float4*)(wb + 2*256*SWS + q*4);
            float4 w3 = *(const float4*)(wb + 3*256*SWS + q*4);
            float l0[4] = {w0.x,w0.y,w0.z,w0.w};
            float l1[4] = {w1.x,w1.y,w1.z,w1.w};
            float l2[4] = {w2.x,w2.y,w2.z,w2.w};
            float l3[4] = {w3.x,w3.y,w3.z,w3.w};
            #pragma unroll
            for (int j = 0; j < 4; j++) {
                const unsigned long long* bp = s_bm + ((kc*16 + q*4 + j) << 4);
                unsigned long long wp0 = packdup(l0[j]);
                unsigned long long wp1 = packdup(l1[j]);
                unsigned long long wp2 = packdup(l2[j]);
                unsigned long long wp3 = packdup(l3[j]);
                #pragma unroll
                for (int n2 = 0; n2 < 16; n2++) {
                    unsigned long long bb = bp[n2];
                    acc[0][n2] = fma2(wp0, bb, acc[0][n2]);
                    acc[1][n2] = fma2(wp1, bb, acc[1][n2]);
                    acc[2][n2] = fma2(wp2, bb, acc[2][n2]);
                    acc[3][n2] = fma2(wp3, bb, acc[3][n2]);
                }
            }
        }
        __syncthreads();
    }

    // store directly transposed: g_T[b][r], lanes have consecutive r -> coalesced
    #pragma unroll
    for (int i = 0; i < 4; i++) {
        long r = r0 + tid + i*256;
        #pragma unroll
        for (int n2 = 0; n2 < 16; n2++) {
            float2 p = unpack2(acc[i][n2]);
            g_T[(long)(2*n2  )*NROW + r] = p.x;
            g_T[(long)(2*n2+1)*NROW + r] = p.y;
        }
    }
}

// ---------------- kernel 3: fused = feat_a @ T^T (+bias +feat_a) ----------------
// tile 128x128x16, 256 thr (16x16), 8x8 microtile, single smem buffer, LDG->regs pipeline
#define GBM 128
#define GBN 128
#define GPAD 132

__global__ void __launch_bounds__(256) k_gemm2(const float* __restrict__ A,
                                               const float* __restrict__ bias,
                                               float* __restrict__ out) {
    __shared__ float sA[16][GPAD];
    __shared__ float sB[16][GPAD];
    int b = blockIdx.z, rt = blockIdx.y, kt = blockIdx.x;
    int tid = threadIdx.x;
    int tx = tid & 15, ty = tid >> 4;
    int row0 = rt * GBM;
    const float* Ab = A + (long)b*LA*H;
    const float* Bb = g_T + (long)b*NROW + (long)kt*GBN*H;

    int lr = tid >> 2;        // 0..63  (loader row within half)
    int lc = tid & 3;         // float4 col

    float4 rA[2], rB[2];
    const float4 z4 = make_float4(0.f,0.f,0.f,0.f);

    // load chunk kc into regs
    auto ldg_chunk = [&](int kc) {
        #pragma unroll
        for (int h = 0; h < 2; h++) {
            int r = lr + h*64;
            int ar = row0 + r;
            rA[h] = (ar < LA) ? *(const float4*)(Ab + (long)ar*H + kc*16 + lc*4) : z4;
            rB[h] = *(const float4*)(Bb + (long)r*H + kc*16 + lc*4);
        }
    };
    auto sts_chunk = [&]() {
        #pragma unroll
        for (int h = 0; h < 2; h++) {
            int r = lr + h*64;
            sA[lc*4+0][r] = rA[h].x; sA[lc*4+1][r] = rA[h].y;
            sA[lc*4+2][r] = rA[h].z; sA[lc*4+3][r] = rA[h].w;
            sB[lc*4+0][r] = rB[h].x; sB[lc*4+1][r] = rB[h].y;
            sB[lc*4+2][r] = rB[h].z; sB[lc*4+3][r] = rB[h].w;
        }
    };

    unsigned long long acc[8][4];
    #pragma unroll
    for (int i = 0; i < 8; i++)
        #pragma unroll
        for (int j = 0; j < 4; j++) acc[i][j] = 0ull;

    ldg_chunk(0);
    sts_chunk();
    __syncthreads();

    for (int kc = 0; kc < 32; kc++) {
        if (kc + 1 < 32) ldg_chunk(kc+1);
        #pragma unroll
        for (int kk = 0; kk < 16; kk++) {
            float4 a0 = *(const float4*)&sA[kk][ty*8];
            float4 a1 = *(const float4*)&sA[kk][ty*8+4];
            ulonglong2 b0 = *(const ulonglong2*)&sB[kk][tx*8];
            ulonglong2 b1 = *(const ulonglong2*)&sB[kk][tx*8+4];
            float av[8] = {a0.x,a0.y,a0.z,a0.w, a1.x,a1.y,a1.z,a1.w};
            #pragma unroll
            for (int i = 0; i < 8; i++) {
                unsigned long long ap = packdup(av[i]);
                acc[i][0] = fma2(ap, b0.x, acc[i][0]);
                acc[i][1] = fma2(ap, b0.y, acc[i][1]);
                acc[i][2] = fma2(ap, b1.x, acc[i][2]);
                acc[i][3] = fma2(ap, b1.y, acc[i][3]);
            }
        }
        __syncthreads();
        if (kc + 1 < 32) {
            sts_chunk();
            __syncthreads();
        }
    }

    int k0 = kt*GBN + tx*8;
    const float4 bias0 = *(const float4*)(bias + k0);
    const float4 bias1 = *(const float4*)(bias + k0 + 4);
    #pragma unroll
    for (int i = 0; i < 8; i++) {
        int ar = row0 + ty*8 + i;
        if (ar < LA) {
            const float4 fa0 = *(const float4*)(Ab + (long)ar*H + k0);
            const float4 fa1 = *(const float4*)(Ab + (long)ar*H + k0 + 4);
            float2 p0 = unpack2(acc[i][0]), p1 = unpack2(acc[i][1]);
            float2 p2 = unpack2(acc[i][2]), p3 = unpack2(acc[i][3]);
            float4 o0 = make_float4(p0.x + bias0.x + fa0.x, p0.y + bias0.y + fa0.y,
                                    p1.x + bias0.z + fa0.z, p1.y + bias0.w + fa0.w);
            float4 o1 = make_float4(p2.x + bias1.x + fa1.x, p2.y + bias1.y + fa1.y,
                                    p3.x + bias1.z + fa1.z, p3.y + bias1.w + fa1.w);
            float* orow = out + ((long)b*LA + ar)*H + k0;
            *(float4*)(orow)     = o0;
            *(float4*)(orow + 4) = o1;
        }
    }
}

// ---------------- kernel 4: LayerNorm in-place ----------------
__global__ void k_ln(const float* __restrict__ gamma, const float* __restrict__ beta,
                     float* __restrict__ out) {
    __shared__ float ssum[4], ssq[4];
    long row = blockIdx.x;
    int tid = threadIdx.x;
    float4* xr = reinterpret_cast<float4*>(out + row*H);
    float4 v = xr[tid];
    float s  = v.x + v.y + v.z + v.w;
    float sq = v.x*v.x + v.y*v.y + v.z*v.z + v.w*v.w;
    #pragma unroll
    for (int o = 16; o > 0; o >>= 1) {
        s  += __shfl_xor_sync(0xffffffffu, s,  o);
        sq += __shfl_xor_sync(0xffffffffu, sq, o);
    }
    int wid = tid >> 5;
    if ((tid & 31) == 0) { ssum[wid] = s; ssq[wid] = sq; }
    __syncthreads();
    float stot = ssum[0] + ssum[1] + ssum[2] + ssum[3];
    float sqtot = ssq[0] + ssq[1] + ssq[2] + ssq[3];
    float mu = stot * (1.0f/H);
    float var = sqtot * (1.0f/H) - mu*mu;
    float rstd = rsqrtf(var + 1e-5f);
    const float4 g4 = reinterpret_cast<const float4*>(gamma)[tid];
    const float4 b4 = reinterpret_cast<const float4*>(beta)[tid];
    v.x = (v.x - mu)*rstd*g4.x + b4.x;
    v.y = (v.y - mu)*rstd*g4.y + b4.y;
    v.z = (v.z - mu)*rstd*g4.z + b4.z;
    v.w = (v.w - mu)*rstd*g4.w + b4.w;
    xr[tid] = v;
}

// ---------------- launch ----------------
extern "C" void kernel_launch(void* const* d_in, const int* in_sizes, int n_in,
                              void* d_out, int out_size) {
    const float* feat_a = (const float*)d_in[0];
    const float* feat_b = (const float*)d_in[1];
    const float* W      = (const float*)d_in[2];
    const float* bias   = (const float*)d_in[3];
    const float* gamma  = (const float*)d_in[4];
    const float* beta   = (const float*)d_in[5];
    float* out = (float*)d_out;

    static bool attr_done = false;
    if (!attr_done) {
        cudaFuncSetAttribute(k_wgemm, cudaFuncAttributeMaxDynamicSharedMemorySize, 229376);
        attr_done = true;
    }

    k_bmean_part<<<dim3(8,32), 512>>>(feat_b);
    k_bmean_red<<<32, 512>>>();
    k_wgemm<<<256, 256, 229376>>>(W);
    k_gemm2<<<dim3(4,3,32), 256>>>(feat_a, bias, out);
    k_ln<<<9600, 128>>>(gamma, beta, out);
}